// round 16
// baseline (speedup 1.0000x reference)
#include <cuda_runtime.h>
#include <cuda_bf16.h>
#include <stdint.h>
#include <math.h>

#define Bc 8
#define Tc 256
#define Nn 118
#define Fc 3
#define Dc 128
#define Ec 372
#define Gc (Bc*Tc)          // 2048 graphs
#define Mc (Gc*Nn)          // 241664 rows
#define CLN 4               // cluster size for LSTM
#define HST 132             // Hg row stride (floats)
#define KP 68               // packed bf16 k-pair row stride (u32)

// ---------------- scratch (device globals; no allocation allowed) ----------------
__device__ __align__(16) float    g_emb[Gc*Dc];
__device__ __align__(16) float    g_xg0[(size_t)Gc*4*Dc];
__device__ __align__(16) float    g_final[Bc*Dc];
__device__ int      g_rowoff[Nn+1];
__device__ int      g_csrsrc[Ec];
__device__ float    g_csrnorm[Ec];
__device__ float    g_invdeg[Nn];
__device__ __align__(16) uint32_t g_Wb2[128*KP];   // W2 as bf16x2, [n][k/2], pre-transposed
__device__ __align__(16) uint32_t g_Wb3[128*KP];

__device__ __forceinline__ float fsig(float x){ return __fdividef(1.0f, 1.0f + __expf(-x)); }
__device__ __forceinline__ float siluf_(float x){ return x*fsig(x); }
__device__ __forceinline__ float tanhap(float x){
    float y; asm("tanh.approx.f32 %0, %1;" : "=f"(y) : "f"(x)); return y;
}
__device__ __forceinline__ float sigap(float x){ return fmaf(0.5f, tanhap(0.5f*x), 0.5f); }

__device__ __forceinline__ uint32_t s2u(const void* p){
    uint32_t a;
    asm("{ .reg .u64 t; cvta.to.shared.u64 t, %1; cvt.u32.u64 %0, t; }" : "=r"(a) : "l"(p));
    return a;
}
__device__ __forceinline__ void st_async_f32(uint32_t laddr, uint32_t lmbar, uint32_t peer, float v){
    asm volatile("{ .reg .b32 ra, rb;\n\t"
                 "mapa.shared::cluster.u32 ra, %0, %2;\n\t"
                 "mapa.shared::cluster.u32 rb, %1, %2;\n\t"
                 "st.async.shared::cluster.mbarrier::complete_tx::bytes.b32 [ra], %3, [rb]; }"
                 :: "r"(laddr), "r"(lmbar), "r"(peer), "r"(__float_as_uint(v)) : "memory");
}
__device__ __forceinline__ void mbar_expect_tx(uint32_t mbar, uint32_t bytes){
    asm volatile("mbarrier.arrive.expect_tx.shared.b64 _, [%0], %1;"
                 :: "r"(mbar), "r"(bytes) : "memory");
}
__device__ __forceinline__ void mbar_wait(uint32_t addr, uint32_t parity){
    asm volatile("{\n\t"
        ".reg .pred P;\n\t"
        "WL%=:\n\t"
        "mbarrier.try_wait.parity.acquire.cluster.shared::cta.b64 P, [%0], %1, 0x989680;\n\t"
        "@!P bra WL%=;\n\t"
        "}" :: "r"(addr), "r"(parity) : "memory");
}
#define FMA2(acc, a, b) \
    asm("fma.rn.f32x2 %0, %1, %2, %0;" : "+l"(acc) : "l"(a), "l"(b))
#define PACK2(out, s) \
    asm("mov.b64 %0, {%1, %1};" : "=l"(out) : "f"(s))
#define UNPACK2(lo, hi, in) \
    asm("mov.b64 {%0, %1}, %2;" : "=f"(lo), "=f"(hi) : "l"(in))

// ---------------- prep: decode edge_index (int32 or int64), build CSR ----------------
__global__ void k_prep(const int* __restrict__ ei) {
    if (threadIdx.x != 0) return;
    int ssrc[Ec], sdst[Ec];
    bool is64 = true;
    for (int i = 1; i < 2*Ec; i += 2) { if (ei[i] != 0) { is64 = false; break; } }
    for (int e = 0; e < Ec; e++) {
        if (is64) { ssrc[e] = ei[2*e]; sdst[e] = ei[2*(Ec+e)]; }
        else      { ssrc[e] = ei[e];   sdst[e] = ei[Ec+e];     }
    }
    float deg[Nn];
    for (int n = 0; n < Nn; n++) deg[n] = 1.0f;
    for (int e = 0; e < Ec; e++) deg[sdst[e]] += 1.0f;
    float inv[Nn];
    for (int n = 0; n < Nn; n++) {
        g_invdeg[n] = 1.0f/deg[n];
        inv[n] = 1.0f/sqrtf(deg[n]);
    }
    int cnt[Nn];
    for (int n = 0; n < Nn; n++) cnt[n] = 0;
    for (int e = 0; e < Ec; e++) cnt[sdst[e]]++;
    int off = 0;
    for (int n = 0; n < Nn; n++) { g_rowoff[n] = off; off += cnt[n]; cnt[n] = g_rowoff[n]; }
    g_rowoff[Nn] = off;
    for (int e = 0; e < Ec; e++) {
        int d = sdst[e]; int p = cnt[d]++;
        g_csrsrc[p]  = ssrc[e];
        g_csrnorm[p] = inv[ssrc[e]] * inv[d];
    }
}

// ---------------- prepw: W2/W3 -> bf16x2 packed col-major-k layout ----------------
__global__ void k_prepw(const float* __restrict__ W2, const float* __restrict__ W3) {
    int i = blockIdx.x * blockDim.x + threadIdx.x;
    if (i >= 128*KP) return;
    int n = i / KP, k2 = i % KP;
    uint32_t v2 = 0, v3 = 0;
    if (k2 < 64) {
        __nv_bfloat162 h2, h3;
        h2.x = __float2bfloat16_rn(W2[(2*k2)*128 + n]);
        h2.y = __float2bfloat16_rn(W2[(2*k2+1)*128 + n]);
        h3.x = __float2bfloat16_rn(W3[(2*k2)*128 + n]);
        h3.y = __float2bfloat16_rn(W3[(2*k2+1)*128 + n]);
        v2 = *(uint32_t*)&h2;
        v3 = *(uint32_t*)&h3;
    }
    g_Wb2[i] = v2;
    g_Wb3[i] = v3;
}

// ---------------- mega: whole GCN stack per graph, bf16 GEMMs + packed-f32x2 aggs ----------
// dyn smem: Hg fp32[128*HST] | HsB bf16x2 u32[128*KP] | Ws bf16x2 u32[128*KP]
__global__ void __launch_bounds__(512,1) k_mega(const float* __restrict__ snap,
        const float* __restrict__ scale, const float* __restrict__ shift,
        const float* __restrict__ W1, const float* __restrict__ b1,
        const float* __restrict__ b2, const float* __restrict__ b3) {
    extern __shared__ float dyn[];
    float*    Hg  = dyn;
    uint32_t* HsB = (uint32_t*)(dyn + 128*HST);
    uint32_t* Ws  = HsB + 128*KP;
    __shared__ int    soff[Nn+1];
    __shared__ int    ssrc[Ec];
    __shared__ float  snorm[Ec];
    __shared__ float  sinvd[Nn];
    __shared__ __align__(16) float  xs[Nn*Fc];
    __shared__ __align__(16) float  sW1[Fc*Dc];
    __shared__ __align__(16) float2 sred2[512];

    int t = threadIdx.x;
    int g = blockIdx.x;
    int cp = t & 63;        // column-pair index (cols 2cp, 2cp+1)
    int qg = t >> 6;        // node group 0..7

    for (int i = t; i < Nn*Fc; i += 512) {
        int f = i - (i/3)*3;
        xs[i] = snap[(size_t)g*Nn*Fc + i]*scale[f] + shift[f];
    }
    for (int i = t; i < Fc*Dc; i += 512) sW1[i] = W1[i];
    for (int i = t; i <= Nn; i += 512) soff[i] = g_rowoff[i];
    for (int i = t; i < Ec; i += 512) { ssrc[i] = g_csrsrc[i]; snorm[i] = g_csrnorm[i]; }
    if (t < Nn) sinvd[t] = g_invdeg[t];
    for (int i = t; i < 128*KP; i += 512) Ws[i] = g_Wb2[i];
    for (int i = t; i < 10*KP; i += 512) HsB[(Nn + i/KP)*KP + (i%KP)] = 0;
    __syncthreads();

    // GEMM1 (K=3, fp32, paired columns) -> Hg
    for (int i = t; i < Nn*64; i += 512) {
        int n = i >> 6, p = i & 63;
        float2 w0 = *(const float2*)&sW1[2*p];
        float2 w1 = *(const float2*)&sW1[128 + 2*p];
        float2 w2 = *(const float2*)&sW1[256 + 2*p];
        float x0 = xs[n*3], x1 = xs[n*3+1], x2 = xs[n*3+2];
        float2 r;
        r.x = fmaf(x0, w0.x, fmaf(x1, w1.x, x2*w2.x));
        r.y = fmaf(x0, w0.y, fmaf(x1, w1.y, x2*w2.y));
        *(float2*)&Hg[n*HST + 2*p] = r;
    }
    __syncthreads();

    // packed agg: Hg -> HsB (silu, bf16x2 single-word store)
    #define DO_AGGP(BIAS) do { \
        float bx = (BIAS)[2*cp], by = (BIAS)[2*cp+1]; \
        for (int n = qg; n < Nn; n += 8) { \
            unsigned long long accp = *(const unsigned long long*)&Hg[n*HST + 2*cp]; \
            unsigned long long sdp; PACK2(sdp, sinvd[n]); \
            { unsigned long long z; asm("mov.b64 %0, {%1, %1};" : "=l"(z) : "r"(0u)); \
              unsigned long long tmp = accp; accp = z; FMA2(accp, tmp, sdp); } \
            int e0 = soff[n], e1 = soff[n+1]; \
            for (int e = e0; e < e1; e++) { \
                unsigned long long hv = *(const unsigned long long*)&Hg[ssrc[e]*HST + 2*cp]; \
                unsigned long long sn; PACK2(sn, snorm[e]); \
                FMA2(accp, hv, sn); \
            } \
            float ax, ay; UNPACK2(ax, ay, accp); \
            float vx = siluf_(ax + bx), vy = siluf_(ay + by); \
            uint32_t w_; asm("cvt.rn.bf16x2.f32 %0, %1, %2;" : "=r"(w_) : "f"(vy), "f"(vx)); \
            HsB[n*KP + cp] = w_; \
        } \
    } while(0)

    DO_AGGP(b1);
    __syncthreads();

    int wid = t >> 5, lane = t & 31;
    int mbase = (wid & 7) * 16, nhalf = (wid >> 3) * 64;
    int gq = lane >> 2, tig = lane & 3;

    // bf16 m16n8k16 GEMM: Hg = HsB @ Ws
    #define DO_GEMM() do { \
        float acc[8][4]; \
        _Pragma("unroll") \
        for (int j = 0; j < 8; j++) { acc[j][0]=0.f; acc[j][1]=0.f; acc[j][2]=0.f; acc[j][3]=0.f; } \
        const uint32_t* Ar0 = HsB + (mbase+gq)*KP; \
        const uint32_t* Ar1 = HsB + (mbase+gq+8)*KP; \
        const uint32_t* Bb  = Ws  + (nhalf+gq)*KP; \
        for (int kk = 0; kk < 64; kk += 8) { \
            uint32_t a0 = Ar0[kk+tig]; \
            uint32_t a1 = Ar1[kk+tig]; \
            uint32_t a2 = Ar0[kk+tig+4]; \
            uint32_t a3 = Ar1[kk+tig+4]; \
            _Pragma("unroll") \
            for (int j = 0; j < 8; j++) { \
                uint32_t b0 = Bb[j*(8*KP) + kk + tig]; \
                uint32_t b1_ = Bb[j*(8*KP) + kk + tig + 4]; \
                asm volatile("mma.sync.aligned.m16n8k16.row.col.f32.bf16.bf16.f32 " \
                    "{%0,%1,%2,%3}, {%4,%5,%6,%7}, {%8,%9}, {%0,%1,%2,%3};" \
                    : "+f"(acc[j][0]), "+f"(acc[j][1]), "+f"(acc[j][2]), "+f"(acc[j][3]) \
                    : "r"(a0), "r"(a1), "r"(a2), "r"(a3), "r"(b0), "r"(b1_)); \
            } \
        } \
        _Pragma("unroll") \
        for (int j = 0; j < 8; j++) { \
            float* o0 = Hg + (mbase+gq)*HST   + nhalf + 8*j + 2*tig; \
            float* o1 = Hg + (mbase+gq+8)*HST + nhalf + 8*j + 2*tig; \
            o0[0] = acc[j][0]; o0[1] = acc[j][1]; \
            o1[0] = acc[j][2]; o1[1] = acc[j][3]; \
        } \
    } while(0)

    DO_GEMM();           // GEMM2
    __syncthreads();

    DO_AGGP(b2);
    for (int i = t; i < 128*KP; i += 512) Ws[i] = g_Wb3[i];
    __syncthreads();

    DO_GEMM();           // GEMM3
    __syncthreads();

    // packed agg3 + silu + mean
    {
        float bx = b3[2*cp], by = b3[2*cp+1];
        float2 macc = make_float2(0.f, 0.f);
        for (int n = qg; n < Nn; n += 8) {
            unsigned long long accp = *(const unsigned long long*)&Hg[n*HST + 2*cp];
            unsigned long long sdp; PACK2(sdp, sinvd[n]);
            { unsigned long long z; asm("mov.b64 %0, {%1, %1};" : "=l"(z) : "r"(0u));
              unsigned long long tmp = accp; accp = z; FMA2(accp, tmp, sdp); }
            int e0 = soff[n], e1 = soff[n+1];
            for (int e = e0; e < e1; e++) {
                unsigned long long hv = *(const unsigned long long*)&Hg[ssrc[e]*HST + 2*cp];
                unsigned long long sn; PACK2(sn, snorm[e]);
                FMA2(accp, hv, sn);
            }
            float ax, ay; UNPACK2(ax, ay, accp);
            macc.x += siluf_(ax + bx);
            macc.y += siluf_(ay + by);
        }
        sred2[t] = macc;
        __syncthreads();
        if (t < 64) {
            float2 s = make_float2(0.f, 0.f);
            #pragma unroll
            for (int k = 0; k < 8; k++) {
                float2 v = sred2[k*64 + t];
                s.x += v.x; s.y += v.y;
            }
            s.x *= (1.0f/(float)Nn);
            s.y *= (1.0f/(float)Nn);
            *(float2*)&g_emb[g*Dc + 2*t] = s;
        }
    }
    #undef DO_GEMM
    #undef DO_AGGP
}

// ---------------- xg0 = emb @ Wih0^T + bih0 + bhh0 (PERMUTED for k_lstm4) ----------------
__global__ void __launch_bounds__(512) k_xg0(const float* __restrict__ Wih0,
        const float* __restrict__ bih0, const float* __restrict__ bhh0) {
    __shared__ __align__(16) float es[16*128];
    int j = threadIdx.x;
    int m0 = blockIdx.x * 16;
    for (int i = j; i < 2048; i += 512) es[i] = g_emb[m0*128 + i];
    __syncthreads();
    const float4* wr = (const float4*)(Wih0 + (size_t)j*128);
    float acc[16];
    #pragma unroll
    for (int r = 0; r < 16; r++) acc[r] = 0.f;
    #pragma unroll 4
    for (int k4 = 0; k4 < 32; k4++) {
        float4 w = wr[k4];
        #pragma unroll
        for (int r = 0; r < 16; r++) {
            float4 e = *(const float4*)&es[r*128 + k4*4];
            acc[r] += w.x*e.x + w.y*e.y + w.z*e.z + w.w*e.w;
        }
    }
    float bb = bih0[j] + bhh0[j];
    int q = j >> 7, e = j & 127;
    int cr = e >> 5, l = e & 31;
    int pidx = cr*128 + q*32 + l;
    #pragma unroll
    for (int r = 0; r < 16; r++)
        g_xg0[(size_t)(m0+r)*512 + pidx] = acc[r] + bb;
}

// ---------------- LSTM v4d: packed f32x2 dots, tanh.approx, distance-1 xv prefetch ----
__global__ void __launch_bounds__(384,1) __cluster_dims__(CLN,1,1)
k_lstm4(const float* __restrict__ Whh0, const float* __restrict__ Wih1,
        const float* __restrict__ Whh1,
        const float* __restrict__ bih1, const float* __restrict__ bhh1) {
    __shared__ __align__(16) float h0buf[2][128];
    __shared__ __align__(16) float h1buf[2][128];
    __shared__ float sg[384];
    __shared__ __align__(8) unsigned long long mbs[2];

    int t    = threadIdx.x;
    int grp  = t >> 7;           // 0,1,2
    int gt   = t & 127;
    int q    = gt >> 5;
    int lane = gt & 31;
    int cta  = blockIdx.x & (CLN-1);
    int b    = blockIdx.x / CLN;
    int grow = q*128 + cta*32 + lane;

    const float* Wsel = (grp == 0) ? Whh0 : (grp == 1) ? Wih1 : Whh1;
    unsigned long long wp[64];
    {
        const ulonglong2* gsrc = (const ulonglong2*)(Wsel + (size_t)grow*128);
        #pragma unroll
        for (int k = 0; k < 32; k++) {
            ulonglong2 v = gsrc[k];
            wp[2*k] = v.x; wp[2*k+1] = v.y;
        }
    }
    float bias1 = (grp == 1) ? (bih1[grow] + bhh1[grow]) : 0.f;

    if (t < 128) { h0buf[0][t] = 0.f; h0buf[1][t] = 0.f; h1buf[0][t] = 0.f; h1buf[1][t] = 0.f; }
    uint32_t mba0 = s2u(&mbs[0]), mba1 = s2u(&mbs[1]);
    uint32_t h0a = s2u(h0buf), h1a = s2u(h1buf);
    if (t == 0) {
        asm volatile("mbarrier.init.shared.b64 [%0], %1;" :: "r"(mba0), "r"(1) : "memory");
        asm volatile("mbarrier.init.shared.b64 [%0], %1;" :: "r"(mba1), "r"(1) : "memory");
    }
    __syncthreads();
    asm volatile("barrier.cluster.arrive.aligned;" ::: "memory");
    asm volatile("barrier.cluster.wait.aligned;"   ::: "memory");

    float c0 = 0.f, c1 = 0.f;
    const float* xg = g_xg0 + (size_t)b*256*512 + cta*128 + gt;  // grp0 threads only

    // prefetch xv for step 0
    float xv = (grp == 0) ? __ldg(&xg[0]) : 0.f;

    for (int s = 0; s < 257; s++) {
        int p = s & 1;
        bool last = (s == 256);
        uint32_t mba = (s & 1) ? mba1 : mba0;
        uint32_t parity = (uint32_t)((s >> 1) & 1);
        if (t == 0 && !last) mbar_expect_tx(mba, 1024u);
        // distance-1 prefetch of next step's xv (off the critical path)
        float xvn = (grp == 0 && s < 255) ? __ldg(&xg[(size_t)(s+1)*512]) : 0.f;
        {
            const ulonglong2* hv = (grp == 2) ? (const ulonglong2*)h1buf[p]
                                              : (const ulonglong2*)h0buf[p];
            unsigned long long acc0, acc1;
            asm("mov.b64 %0, {%1, %1};" : "=l"(acc0) : "r"(0u));
            asm("mov.b64 %0, {%1, %1};" : "=l"(acc1) : "r"(0u));
            #pragma unroll
            for (int k = 0; k < 32; k++) {
                ulonglong2 h = hv[k];
                FMA2(acc0, wp[2*k],   h.x);
                FMA2(acc1, wp[2*k+1], h.y);
            }
            float r0, r1, r2, r3;
            asm("mov.b64 {%0, %1}, %2;" : "=f"(r0), "=f"(r1) : "l"(acc0));
            asm("mov.b64 {%0, %1}, %2;" : "=f"(r2), "=f"(r3) : "l"(acc1));
            float d = (r0 + r1) + (r2 + r3);
            if (grp == 0) d += (last ? 0.f : xv);
            else if (grp == 1) d += bias1;
            sg[t] = d;
        }
        __syncthreads();
        if (t < 32 && !last) {
            float gi = sg[t], gf = sg[32+t], gg = sg[64+t], go = sg[96+t];
            c0 = sigap(gf)*c0 + sigap(gi)*tanhap(gg);
            float hv0 = sigap(go)*tanhap(c0);
            uint32_t dst = h0a + (uint32_t)(((p^1)*128 + cta*32 + t)*4);
            #pragma unroll
            for (int peer = 0; peer < CLN; peer++)
                st_async_f32(dst, mba, (uint32_t)peer, hv0);
        }
        if (t >= 32 && t < 64) {
            int l = t - 32;
            float hv1;
            if (s == 0) {
                hv1 = 0.f;
            } else {
                float gi = sg[128+l]      + sg[256+l];
                float gf = sg[128+32+l]   + sg[256+32+l];
                float gg = sg[128+64+l]   + sg[256+64+l];
                float go = sg[128+96+l]   + sg[256+96+l];
                c1 = sigap(gf)*c1 + sigap(gi)*tanhap(gg);
                hv1 = sigap(go)*tanhap(c1);
            }
            if (!last) {
                uint32_t dst = h1a + (uint32_t)(((p^1)*128 + cta*32 + l)*4);
                #pragma unroll
                for (int peer = 0; peer < CLN; peer++)
                    st_async_f32(dst, mba, (uint32_t)peer, hv1);
            } else {
                g_final[b*128 + cta*32 + l] = hv1;
            }
        }
        xv = xvn;
        if (!last) mbar_wait(mba, parity);
    }
}

// ---------------- head MLP ----------------
__global__ void __launch_bounds__(128) k_head(const float* __restrict__ hW1, const float* __restrict__ hb1,
        const float* __restrict__ hW2, const float* __restrict__ hb2,
        const float* __restrict__ hW3, const float* __restrict__ hb3,
        float* __restrict__ out) {
    __shared__ float sf[8*128], s1[8*128], s2[8*64];
    int t = threadIdx.x;
    for (int i = t; i < 1024; i += 128) sf[i] = g_final[i];
    __syncthreads();
    {
        int d = t;
        for (int b = 0; b < 8; b++) {
            float acc = hb1[d];
            for (int k = 0; k < 128; k++) acc += sf[b*128+k]*hW1[k*128+d];
            s1[b*128+d] = siluf_(acc);
        }
    }
    __syncthreads();
    if (t < 64) {
        int e = t;
        for (int b = 0; b < 8; b++) {
            float acc = hb2[e];
            for (int k = 0; k < 128; k++) acc += s1[b*128+k]*hW2[k*64+e];
            s2[b*64+e] = siluf_(acc);
        }
    }
    __syncthreads();
    if (t < 16) {
        int b = t >> 1, o = t & 1;
        float acc = hb3[o];
        for (int k = 0; k < 64; k++) acc += s2[b*64+k]*hW3[k*2+o];
        float sp = fmaxf(acc, 0.f) + log1pf(expf(-fabsf(acc)));
        out[b*2+o] = sp + 1e-6f;
    }
}

// ---------------- launch ----------------
extern "C" void kernel_launch(void* const* d_in, const int* in_sizes, int n_in,
                              void* d_out, int out_size) {
    const float* snap  = (const float*)d_in[0];
    const int*   ei    = (const int*)  d_in[1];
    const float* scale = (const float*)d_in[2];
    const float* shift = (const float*)d_in[3];
    const float* W1    = (const float*)d_in[4];
    const float* b1    = (const float*)d_in[5];
    const float* W2    = (const float*)d_in[6];
    const float* b2    = (const float*)d_in[7];
    const float* W3    = (const float*)d_in[8];
    const float* b3    = (const float*)d_in[9];
    const float* Wih0  = (const float*)d_in[10];
    const float* Whh0  = (const float*)d_in[11];
    const float* bih0  = (const float*)d_in[12];
    const float* bhh0  = (const float*)d_in[13];
    const float* Wih1  = (const float*)d_in[14];
    const float* Whh1  = (const float*)d_in[15];
    const float* bih1  = (const float*)d_in[16];
    const float* bhh1  = (const float*)d_in[17];
    const float* hW1   = (const float*)d_in[18];
    const float* hb1   = (const float*)d_in[19];
    const float* hW2   = (const float*)d_in[20];
    const float* hb2   = (const float*)d_in[21];
    const float* hW3   = (const float*)d_in[22];
    const float* hb3   = (const float*)d_in[23];
    float* out = (float*)d_out;

    const int megaSmem = (128*HST)*(int)sizeof(float) + 2*(128*KP)*(int)sizeof(uint32_t); // 137216
    cudaFuncSetAttribute(k_mega, cudaFuncAttributeMaxDynamicSharedMemorySize, megaSmem);

    k_prep<<<1, 32>>>(ei);
    k_prepw<<<(128*KP + 255)/256, 256>>>(W2, W3);
    k_mega<<<Gc, 512, megaSmem>>>(snap, scale, shift, W1, b1, b2, b3);
    k_xg0<<<Gc/16, 512>>>(Wih0, bih0, bhh0);
    k_lstm4<<<Bc*CLN, 384>>>(Whh0, Wih1, Whh1, bih1, bhh1);
    k_head<<<1, 128>>>(hW1, hb1, hW2, hb2, hW3, hb3, out);
}

// round 17
// speedup vs baseline: 1.0247x; 1.0247x over previous
#include <cuda_runtime.h>
#include <cuda_bf16.h>
#include <stdint.h>
#include <math.h>

#define Bc 8
#define Tc 256
#define Nn 118
#define Fc 3
#define Dc 128
#define Ec 372
#define Gc (Bc*Tc)          // 2048 graphs
#define Mc (Gc*Nn)          // 241664 rows
#define CLN 4               // cluster size for LSTM
#define HST 132             // Hg row stride (floats)
#define KP 68               // packed bf16 k-pair row stride (u32)

// ---------------- scratch (device globals; no allocation allowed) ----------------
__device__ __align__(16) float    g_emb[Gc*Dc];
__device__ __align__(16) float    g_xg0[(size_t)Gc*4*Dc];
__device__ __align__(16) float    g_final[Bc*Dc];
__device__ int      g_rowoff[Nn+1];
__device__ int      g_csrsrc[Ec];
__device__ float    g_csrnorm[Ec];
__device__ float    g_invdeg[Nn];
__device__ __align__(16) uint32_t g_Wb2[128*KP];   // W2 as bf16x2, [n][k/2], pre-transposed
__device__ __align__(16) uint32_t g_Wb3[128*KP];

__device__ __forceinline__ float fsig(float x){ return __fdividef(1.0f, 1.0f + __expf(-x)); }
__device__ __forceinline__ float siluf_(float x){ return x*fsig(x); }
__device__ __forceinline__ float tanhap(float x){
    float y; asm("tanh.approx.f32 %0, %1;" : "=f"(y) : "f"(x)); return y;
}
__device__ __forceinline__ float sigap(float x){ return fmaf(0.5f, tanhap(0.5f*x), 0.5f); }

__device__ __forceinline__ uint32_t s2u(const void* p){
    uint32_t a;
    asm("{ .reg .u64 t; cvta.to.shared.u64 t, %1; cvt.u32.u64 %0, t; }" : "=r"(a) : "l"(p));
    return a;
}
__device__ __forceinline__ void st_async_f32(uint32_t laddr, uint32_t lmbar, uint32_t peer, float v){
    asm volatile("{ .reg .b32 ra, rb;\n\t"
                 "mapa.shared::cluster.u32 ra, %0, %2;\n\t"
                 "mapa.shared::cluster.u32 rb, %1, %2;\n\t"
                 "st.async.shared::cluster.mbarrier::complete_tx::bytes.b32 [ra], %3, [rb]; }"
                 :: "r"(laddr), "r"(lmbar), "r"(peer), "r"(__float_as_uint(v)) : "memory");
}
__device__ __forceinline__ void mbar_expect_tx(uint32_t mbar, uint32_t bytes){
    asm volatile("mbarrier.arrive.expect_tx.shared.b64 _, [%0], %1;"
                 :: "r"(mbar), "r"(bytes) : "memory");
}
__device__ __forceinline__ void mbar_wait(uint32_t addr, uint32_t parity){
    asm volatile("{\n\t"
        ".reg .pred P;\n\t"
        "WL%=:\n\t"
        "mbarrier.try_wait.parity.acquire.cluster.shared::cta.b64 P, [%0], %1, 0x989680;\n\t"
        "@!P bra WL%=;\n\t"
        "}" :: "r"(addr), "r"(parity) : "memory");
}
#define FMA2(acc, a, b) \
    asm("fma.rn.f32x2 %0, %1, %2, %0;" : "+l"(acc) : "l"(a), "l"(b))
#define PACK2(out, s) \
    asm("mov.b64 %0, {%1, %1};" : "=l"(out) : "f"(s))
#define UNPACK2(lo, hi, in) \
    asm("mov.b64 {%0, %1}, %2;" : "=f"(lo), "=f"(hi) : "l"(in))

// ---------------- prep: decode edge_index (int32 or int64), build CSR ----------------
__global__ void k_prep(const int* __restrict__ ei) {
    if (threadIdx.x != 0) return;
    int ssrc[Ec], sdst[Ec];
    bool is64 = true;
    for (int i = 1; i < 2*Ec; i += 2) { if (ei[i] != 0) { is64 = false; break; } }
    for (int e = 0; e < Ec; e++) {
        if (is64) { ssrc[e] = ei[2*e]; sdst[e] = ei[2*(Ec+e)]; }
        else      { ssrc[e] = ei[e];   sdst[e] = ei[Ec+e];     }
    }
    float deg[Nn];
    for (int n = 0; n < Nn; n++) deg[n] = 1.0f;
    for (int e = 0; e < Ec; e++) deg[sdst[e]] += 1.0f;
    float inv[Nn];
    for (int n = 0; n < Nn; n++) {
        g_invdeg[n] = 1.0f/deg[n];
        inv[n] = 1.0f/sqrtf(deg[n]);
    }
    int cnt[Nn];
    for (int n = 0; n < Nn; n++) cnt[n] = 0;
    for (int e = 0; e < Ec; e++) cnt[sdst[e]]++;
    int off = 0;
    for (int n = 0; n < Nn; n++) { g_rowoff[n] = off; off += cnt[n]; cnt[n] = g_rowoff[n]; }
    g_rowoff[Nn] = off;
    for (int e = 0; e < Ec; e++) {
        int d = sdst[e]; int p = cnt[d]++;
        g_csrsrc[p]  = ssrc[e];
        g_csrnorm[p] = inv[ssrc[e]] * inv[d];
    }
}

// ---------------- prepw: W2/W3 -> bf16x2 packed col-major-k layout ----------------
__global__ void k_prepw(const float* __restrict__ W2, const float* __restrict__ W3) {
    int i = blockIdx.x * blockDim.x + threadIdx.x;
    if (i >= 128*KP) return;
    int n = i / KP, k2 = i % KP;
    uint32_t v2 = 0, v3 = 0;
    if (k2 < 64) {
        __nv_bfloat162 h2, h3;
        h2.x = __float2bfloat16_rn(W2[(2*k2)*128 + n]);
        h2.y = __float2bfloat16_rn(W2[(2*k2+1)*128 + n]);
        h3.x = __float2bfloat16_rn(W3[(2*k2)*128 + n]);
        h3.y = __float2bfloat16_rn(W3[(2*k2+1)*128 + n]);
        v2 = *(uint32_t*)&h2;
        v3 = *(uint32_t*)&h3;
    }
    g_Wb2[i] = v2;
    g_Wb3[i] = v3;
}

// ---------------- mega2g: TWO graphs per block, both W tiles resident ----------------
// dyn smem: Hg fp32[128*HST] | HsB u32[128*KP] | Ws2 u32[128*KP] | Ws3 u32[128*KP]
__global__ void __launch_bounds__(512,1) k_mega(const float* __restrict__ snap,
        const float* __restrict__ scale, const float* __restrict__ shift,
        const float* __restrict__ W1, const float* __restrict__ b1,
        const float* __restrict__ b2, const float* __restrict__ b3) {
    extern __shared__ float dyn[];
    float*    Hg  = dyn;
    uint32_t* HsB = (uint32_t*)(dyn + 128*HST);
    uint32_t* Ws2 = HsB + 128*KP;
    uint32_t* Ws3 = Ws2 + 128*KP;
    __shared__ int    soff[Nn+1];
    __shared__ int    ssrc[Ec];
    __shared__ float  snorm[Ec];
    __shared__ float  sinvd[Nn];
    __shared__ __align__(16) float  xs[Nn*Fc];
    __shared__ __align__(16) float  sW1[Fc*Dc];
    __shared__ __align__(16) float2 sred2[512];

    int t = threadIdx.x;
    int cp = t & 63;        // column-pair index (cols 2cp, 2cp+1)
    int qg = t >> 6;        // node group 0..7
    int wid = t >> 5, lane = t & 31;
    int mbase = (wid & 7) * 16, nhalf = (wid >> 3) * 64;
    int gq = lane >> 2, tig = lane & 3;

    // ---- prologue: shared across both graphs ----
    for (int i = t; i < Fc*Dc; i += 512) sW1[i] = W1[i];
    for (int i = t; i <= Nn; i += 512) soff[i] = g_rowoff[i];
    for (int i = t; i < Ec; i += 512) { ssrc[i] = g_csrsrc[i]; snorm[i] = g_csrnorm[i]; }
    if (t < Nn) sinvd[t] = g_invdeg[t];
    for (int i = t; i < 128*KP; i += 512) { Ws2[i] = g_Wb2[i]; Ws3[i] = g_Wb3[i]; }
    for (int i = t; i < 10*KP; i += 512) HsB[(Nn + i/KP)*KP + (i%KP)] = 0;

    #define DO_AGGP(BIAS) do { \
        float bx = (BIAS)[2*cp], by = (BIAS)[2*cp+1]; \
        for (int n = qg; n < Nn; n += 8) { \
            unsigned long long accp = *(const unsigned long long*)&Hg[n*HST + 2*cp]; \
            unsigned long long sdp; PACK2(sdp, sinvd[n]); \
            { unsigned long long z; asm("mov.b64 %0, {%1, %1};" : "=l"(z) : "r"(0u)); \
              unsigned long long tmp = accp; accp = z; FMA2(accp, tmp, sdp); } \
            int e0 = soff[n], e1 = soff[n+1]; \
            for (int e = e0; e < e1; e++) { \
                unsigned long long hv = *(const unsigned long long*)&Hg[ssrc[e]*HST + 2*cp]; \
                unsigned long long sn; PACK2(sn, snorm[e]); \
                FMA2(accp, hv, sn); \
            } \
            float ax, ay; UNPACK2(ax, ay, accp); \
            float vx = siluf_(ax + bx), vy = siluf_(ay + by); \
            uint32_t w_; asm("cvt.rn.bf16x2.f32 %0, %1, %2;" : "=r"(w_) : "f"(vy), "f"(vx)); \
            HsB[n*KP + cp] = w_; \
        } \
    } while(0)

    #define DO_GEMM(WSP) do { \
        float acc[8][4]; \
        _Pragma("unroll") \
        for (int j = 0; j < 8; j++) { acc[j][0]=0.f; acc[j][1]=0.f; acc[j][2]=0.f; acc[j][3]=0.f; } \
        const uint32_t* Ar0 = HsB + (mbase+gq)*KP; \
        const uint32_t* Ar1 = HsB + (mbase+gq+8)*KP; \
        const uint32_t* Bb  = (WSP) + (nhalf+gq)*KP; \
        for (int kk = 0; kk < 64; kk += 8) { \
            uint32_t a0 = Ar0[kk+tig]; \
            uint32_t a1 = Ar1[kk+tig]; \
            uint32_t a2 = Ar0[kk+tig+4]; \
            uint32_t a3 = Ar1[kk+tig+4]; \
            _Pragma("unroll") \
            for (int j = 0; j < 8; j++) { \
                uint32_t b0 = Bb[j*(8*KP) + kk + tig]; \
                uint32_t b1_ = Bb[j*(8*KP) + kk + tig + 4]; \
                asm volatile("mma.sync.aligned.m16n8k16.row.col.f32.bf16.bf16.f32 " \
                    "{%0,%1,%2,%3}, {%4,%5,%6,%7}, {%8,%9}, {%0,%1,%2,%3};" \
                    : "+f"(acc[j][0]), "+f"(acc[j][1]), "+f"(acc[j][2]), "+f"(acc[j][3]) \
                    : "r"(a0), "r"(a1), "r"(a2), "r"(a3), "r"(b0), "r"(b1_)); \
            } \
        } \
        _Pragma("unroll") \
        for (int j = 0; j < 8; j++) { \
            float* o0 = Hg + (mbase+gq)*HST   + nhalf + 8*j + 2*tig; \
            float* o1 = Hg + (mbase+gq+8)*HST + nhalf + 8*j + 2*tig; \
            o0[0] = acc[j][0]; o0[1] = acc[j][1]; \
            o1[0] = acc[j][2]; o1[1] = acc[j][3]; \
        } \
    } while(0)

    for (int gg = 0; gg < 2; gg++) {
        int g = blockIdx.x * 2 + gg;
        // load + normalize inputs for this graph
        for (int i = t; i < Nn*Fc; i += 512) {
            int f = i - (i/3)*3;
            xs[i] = snap[(size_t)g*Nn*Fc + i]*scale[f] + shift[f];
        }
        __syncthreads();

        // GEMM1 (K=3, fp32, paired columns) -> Hg
        for (int i = t; i < Nn*64; i += 512) {
            int n = i >> 6, p = i & 63;
            float2 w0 = *(const float2*)&sW1[2*p];
            float2 w1 = *(const float2*)&sW1[128 + 2*p];
            float2 w2 = *(const float2*)&sW1[256 + 2*p];
            float x0 = xs[n*3], x1 = xs[n*3+1], x2 = xs[n*3+2];
            float2 r;
            r.x = fmaf(x0, w0.x, fmaf(x1, w1.x, x2*w2.x));
            r.y = fmaf(x0, w0.y, fmaf(x1, w1.y, x2*w2.y));
            *(float2*)&Hg[n*HST + 2*p] = r;
        }
        __syncthreads();

        DO_AGGP(b1);
        __syncthreads();

        DO_GEMM(Ws2);
        __syncthreads();

        DO_AGGP(b2);
        __syncthreads();

        DO_GEMM(Ws3);
        __syncthreads();

        // packed agg3 + silu + mean
        {
            float bx = b3[2*cp], by = b3[2*cp+1];
            float2 macc = make_float2(0.f, 0.f);
            for (int n = qg; n < Nn; n += 8) {
                unsigned long long accp = *(const unsigned long long*)&Hg[n*HST + 2*cp];
                unsigned long long sdp; PACK2(sdp, sinvd[n]);
                { unsigned long long z; asm("mov.b64 %0, {%1, %1};" : "=l"(z) : "r"(0u));
                  unsigned long long tmp = accp; accp = z; FMA2(accp, tmp, sdp); }
                int e0 = soff[n], e1 = soff[n+1];
                for (int e = e0; e < e1; e++) {
                    unsigned long long hv = *(const unsigned long long*)&Hg[ssrc[e]*HST + 2*cp];
                    unsigned long long sn; PACK2(sn, snorm[e]);
                    FMA2(accp, hv, sn);
                }
                float ax, ay; UNPACK2(ax, ay, accp);
                macc.x += siluf_(ax + bx);
                macc.y += siluf_(ay + by);
            }
            sred2[t] = macc;
            __syncthreads();
            if (t < 64) {
                float2 s = make_float2(0.f, 0.f);
                #pragma unroll
                for (int k = 0; k < 8; k++) {
                    float2 v = sred2[k*64 + t];
                    s.x += v.x; s.y += v.y;
                }
                s.x *= (1.0f/(float)Nn);
                s.y *= (1.0f/(float)Nn);
                *(float2*)&g_emb[g*Dc + 2*t] = s;
            }
        }
        __syncthreads();
    }
    #undef DO_GEMM
    #undef DO_AGGP
}

// ---------------- xg0 = emb @ Wih0^T + bih0 + bhh0 (PERMUTED for k_lstm6) ----------------
__global__ void __launch_bounds__(512) k_xg0(const float* __restrict__ Wih0,
        const float* __restrict__ bih0, const float* __restrict__ bhh0) {
    __shared__ __align__(16) float es[16*128];
    int j = threadIdx.x;
    int m0 = blockIdx.x * 16;
    for (int i = j; i < 2048; i += 512) es[i] = g_emb[m0*128 + i];
    __syncthreads();
    const float4* wr = (const float4*)(Wih0 + (size_t)j*128);
    float acc[16];
    #pragma unroll
    for (int r = 0; r < 16; r++) acc[r] = 0.f;
    #pragma unroll 4
    for (int k4 = 0; k4 < 32; k4++) {
        float4 w = wr[k4];
        #pragma unroll
        for (int r = 0; r < 16; r++) {
            float4 e = *(const float4*)&es[r*128 + k4*4];
            acc[r] += w.x*e.x + w.y*e.y + w.z*e.z + w.w*e.w;
        }
    }
    float bb = bih0[j] + bhh0[j];
    int q = j >> 7, e = j & 127;
    int cr = e >> 5, l = e & 31;
    int pidx = cr*128 + q*32 + l;
    #pragma unroll
    for (int r = 0; r < 16; r++)
        g_xg0[(size_t)(m0+r)*512 + pidx] = acc[r] + bb;
}

// ---------------- LSTM v6: split named barriers per layer chain ----------
// warps 0-3  (grp0): Whh0 dots -> sg[0:128]   ; bar.sync 1,128 ; warp0 acts h0
// warps 4-7  (grp1): Wih1 dots -> sg[128:256] ; bar.sync 2,256 (with grp2)
// warps 8-11 (grp2): Whh1 dots -> sg[256:384] ; warp4 acts h1 (owns c1)
__global__ void __launch_bounds__(384,1) __cluster_dims__(CLN,1,1)
k_lstm6(const float* __restrict__ Whh0, const float* __restrict__ Wih1,
        const float* __restrict__ Whh1,
        const float* __restrict__ bih1, const float* __restrict__ bhh1) {
    __shared__ __align__(16) float h0buf[2][128];
    __shared__ __align__(16) float h1buf[2][128];
    __shared__ float sg[384];
    __shared__ __align__(8) unsigned long long mbs[2];

    int t    = threadIdx.x;
    int grp  = t >> 7;           // 0,1,2
    int gt   = t & 127;
    int q    = gt >> 5;
    int lane = gt & 31;
    int cta  = blockIdx.x & (CLN-1);
    int b    = blockIdx.x / CLN;
    int grow = q*128 + cta*32 + lane;

    const float* Wsel = (grp == 0) ? Whh0 : (grp == 1) ? Wih1 : Whh1;
    unsigned long long wp[64];
    {
        const ulonglong2* gsrc = (const ulonglong2*)(Wsel + (size_t)grow*128);
        #pragma unroll
        for (int k = 0; k < 32; k++) {
            ulonglong2 v = gsrc[k];
            wp[2*k] = v.x; wp[2*k+1] = v.y;
        }
    }
    float bias1 = (grp == 1) ? (bih1[grow] + bhh1[grow]) : 0.f;

    if (t < 128) { h0buf[0][t] = 0.f; h0buf[1][t] = 0.f; h1buf[0][t] = 0.f; h1buf[1][t] = 0.f; }
    uint32_t mba0 = s2u(&mbs[0]), mba1 = s2u(&mbs[1]);
    uint32_t h0a = s2u(h0buf), h1a = s2u(h1buf);
    if (t == 0) {
        asm volatile("mbarrier.init.shared.b64 [%0], %1;" :: "r"(mba0), "r"(1) : "memory");
        asm volatile("mbarrier.init.shared.b64 [%0], %1;" :: "r"(mba1), "r"(1) : "memory");
    }
    __syncthreads();
    asm volatile("barrier.cluster.arrive.aligned;" ::: "memory");
    asm volatile("barrier.cluster.wait.aligned;"   ::: "memory");

    float c0 = 0.f, c1 = 0.f;
    const float* xg = g_xg0 + (size_t)b*256*512 + cta*128 + gt;  // grp0 threads only

    for (int s = 0; s < 257; s++) {
        int p = s & 1;
        bool last = (s == 256);
        uint32_t mba = (s & 1) ? mba1 : mba0;
        uint32_t parity = (uint32_t)((s >> 1) & 1);
        if (t == 0 && !last) mbar_expect_tx(mba, 1024u);
        float xv = (grp == 0 && !last) ? __ldg(&xg[(size_t)s*512]) : 0.f;
        {
            const ulonglong2* hv = (grp == 2) ? (const ulonglong2*)h1buf[p]
                                              : (const ulonglong2*)h0buf[p];
            unsigned long long acc0, acc1;
            asm("mov.b64 %0, {%1, %1};" : "=l"(acc0) : "r"(0u));
            asm("mov.b64 %0, {%1, %1};" : "=l"(acc1) : "r"(0u));
            #pragma unroll
            for (int k = 0; k < 32; k++) {
                ulonglong2 h = hv[k];
                FMA2(acc0, wp[2*k],   h.x);
                FMA2(acc1, wp[2*k+1], h.y);
            }
            float r0, r1, r2, r3;
            asm("mov.b64 {%0, %1}, %2;" : "=f"(r0), "=f"(r1) : "l"(acc0));
            asm("mov.b64 {%0, %1}, %2;" : "=f"(r2), "=f"(r3) : "l"(acc1));
            float d = (r0 + r1) + (r2 + r3);
            if (grp == 0) d += xv;
            else if (grp == 1) d += bias1;
            sg[t] = d;
        }
        if (grp == 0) {
            // layer-0 chain: only warps 0-3 converge
            asm volatile("bar.sync 1, 128;" ::: "memory");
            if (t < 32 && !last) {
                float gi = sg[t], gf = sg[32+t], gg = sg[64+t], go = sg[96+t];
                c0 = sigap(gf)*c0 + sigap(gi)*tanhap(gg);
                float hv0 = sigap(go)*tanhap(c0);
                uint32_t dst = h0a + (uint32_t)(((p^1)*128 + cta*32 + t)*4);
                #pragma unroll
                for (int peer = 0; peer < CLN; peer++)
                    st_async_f32(dst, mba, (uint32_t)peer, hv0);
            }
        } else {
            // layer-1 chain: warps 4-11 converge
            asm volatile("bar.sync 2, 256;" ::: "memory");
            if (t >= 128 && t < 160) {
                int l = t - 128;
                float hv1;
                if (s == 0) {
                    hv1 = 0.f;
                } else {
                    float gi = sg[128+l]      + sg[256+l];
                    float gf = sg[128+32+l]   + sg[256+32+l];
                    float gg = sg[128+64+l]   + sg[256+64+l];
                    float go = sg[128+96+l]   + sg[256+96+l];
                    c1 = sigap(gf)*c1 + sigap(gi)*tanhap(gg);
                    hv1 = sigap(go)*tanhap(c1);
                }
                if (!last) {
                    uint32_t dst = h1a + (uint32_t)(((p^1)*128 + cta*32 + l)*4);
                    #pragma unroll
                    for (int peer = 0; peer < CLN; peer++)
                        st_async_f32(dst, mba, (uint32_t)peer, hv1);
                } else {
                    g_final[b*128 + cta*32 + l] = hv1;
                }
            }
        }
        if (!last) mbar_wait(mba, parity);
    }
}

// ---------------- head MLP ----------------
__global__ void __launch_bounds__(128) k_head(const float* __restrict__ hW1, const float* __restrict__ hb1,
        const float* __restrict__ hW2, const float* __restrict__ hb2,
        const float* __restrict__ hW3, const float* __restrict__ hb3,
        float* __restrict__ out) {
    __shared__ float sf[8*128], s1[8*128], s2[8*64];
    int t = threadIdx.x;
    for (int i = t; i < 1024; i += 128) sf[i] = g_final[i];
    __syncthreads();
    {
        int d = t;
        for (int b = 0; b < 8; b++) {
            float acc = hb1[d];
            for (int k = 0; k < 128; k++) acc += sf[b*128+k]*hW1[k*128+d];
            s1[b*128+d] = siluf_(acc);
        }
    }
    __syncthreads();
    if (t < 64) {
        int e = t;
        for (int b = 0; b < 8; b++) {
            float acc = hb2[e];
            for (int k = 0; k < 128; k++) acc += s1[b*128+k]*hW2[k*64+e];
            s2[b*64+e] = siluf_(acc);
        }
    }
    __syncthreads();
    if (t < 16) {
        int b = t >> 1, o = t & 1;
        float acc = hb3[o];
        for (int k = 0; k < 64; k++) acc += s2[b*64+k]*hW3[k*2+o];
        float sp = fmaxf(acc, 0.f) + log1pf(expf(-fabsf(acc)));
        out[b*2+o] = sp + 1e-6f;
    }
}

// ---------------- launch ----------------
extern "C" void kernel_launch(void* const* d_in, const int* in_sizes, int n_in,
                              void* d_out, int out_size) {
    const float* snap  = (const float*)d_in[0];
    const int*   ei    = (const int*)  d_in[1];
    const float* scale = (const float*)d_in[2];
    const float* shift = (const float*)d_in[3];
    const float* W1    = (const float*)d_in[4];
    const float* b1    = (const float*)d_in[5];
    const float* W2    = (const float*)d_in[6];
    const float* b2    = (const float*)d_in[7];
    const float* W3    = (const float*)d_in[8];
    const float* b3    = (const float*)d_in[9];
    const float* Wih0  = (const float*)d_in[10];
    const float* Whh0  = (const float*)d_in[11];
    const float* bih0  = (const float*)d_in[12];
    const float* bhh0  = (const float*)d_in[13];
    const float* Wih1  = (const float*)d_in[14];
    const float* Whh1  = (const float*)d_in[15];
    const float* bih1  = (const float*)d_in[16];
    const float* bhh1  = (const float*)d_in[17];
    const float* hW1   = (const float*)d_in[18];
    const float* hb1   = (const float*)d_in[19];
    const float* hW2   = (const float*)d_in[20];
    const float* hb2   = (const float*)d_in[21];
    const float* hW3   = (const float*)d_in[22];
    const float* hb3   = (const float*)d_in[23];
    float* out = (float*)d_out;

    const int megaSmem = (128*HST)*(int)sizeof(float) + 3*(128*KP)*(int)sizeof(uint32_t); // 172032
    cudaFuncSetAttribute(k_mega, cudaFuncAttributeMaxDynamicSharedMemorySize, megaSmem);

    k_prep<<<1, 32>>>(ei);
    k_prepw<<<(128*KP + 255)/256, 256>>>(W2, W3);
    k_mega<<<Gc/2, 512, megaSmem>>>(snap, scale, shift, W1, b1, b2, b3);
    k_xg0<<<Gc/16, 512>>>(Wih0, bih0, bhh0);
    k_lstm6<<<Bc*CLN, 384>>>(Whh0, Wih1, Whh1, bih1, bhh1);
    k_head<<<1, 128>>>(hW1, hb1, hW2, hb2, hW3, hb3, out);
}